// round 1
// baseline (speedup 1.0000x reference)
#include <cuda_runtime.h>

// Problem dims (fixed by the reference)
#define Gn   32          // B*S graphs
#define NN   4000        // nodes
#define EE   32000       // edges per graph
#define FD0  64          // input feature dim
#define HD   128         // hidden dim
#define BNR  16000       // B*N LSTM rows
#define STEPS 8

// ---------------- scratch (device globals; no allocations allowed) -------------
__device__ float d_deg_out[Gn * NN];
__device__ float d_deg_in [Gn * NN];
__device__ float d_norm   [Gn * EE];
__device__ float d_aggf   [(size_t)Gn * NN * HD];   // also used compactly as [.,64] for layer0
__device__ float d_aggb   [(size_t)Gn * NN * HD];
__device__ float d_h0     [(size_t)Gn * NN * HD];
__device__ float d_h1     [(size_t)Gn * NN * HD];
__device__ float d_gx     [(size_t)BNR * STEPS * 4 * HD];  // precomputed x@Wih.T + bih + bhh
__device__ float d_hlast  [(size_t)BNR * HD];
__device__ float d_whhT   [HD * 4 * HD];                   // Whh transposed [128][512]

// ---------------- small utility kernels ----------------------------------------
__global__ void zero_deg_kernel() {
    int i = blockIdx.x * blockDim.x + threadIdx.x;
    if (i < Gn * NN) { d_deg_out[i] = 0.f; d_deg_in[i] = 0.f; }
}

__global__ void zero_agg_kernel(int n4) {
    int i = blockIdx.x * blockDim.x + threadIdx.x;
    if (i < n4) {
        ((float4*)d_aggf)[i] = make_float4(0.f, 0.f, 0.f, 0.f);
        ((float4*)d_aggb)[i] = make_float4(0.f, 0.f, 0.f, 0.f);
    }
}

__global__ void degree_kernel(const int* __restrict__ ei, const float* __restrict__ ew) {
    int i = blockIdx.x * blockDim.x + threadIdx.x;
    if (i >= Gn * EE) return;
    int g = i / EE, e = i - g * EE;
    const int* eig = ei + (size_t)g * 2 * EE;
    int src = eig[e], dst = eig[EE + e];
    float w = ew[i];
    atomicAdd(&d_deg_out[g * NN + src], w);
    atomicAdd(&d_deg_in [g * NN + dst], w);
}

__global__ void inv_kernel() {
    int i = blockIdx.x * blockDim.x + threadIdx.x;
    if (i >= Gn * NN) return;
    float v = d_deg_out[i];
    d_deg_out[i] = (v > 0.f) ? rsqrtf(fmaxf(v, 1e-12f)) : 0.f;
    v = d_deg_in[i];
    d_deg_in[i]  = (v > 0.f) ? rsqrtf(fmaxf(v, 1e-12f)) : 0.f;
}

__global__ void norm_kernel(const int* __restrict__ ei, const float* __restrict__ ew) {
    int i = blockIdx.x * blockDim.x + threadIdx.x;
    if (i >= Gn * EE) return;
    int g = i / EE, e = i - g * EE;
    const int* eig = ei + (size_t)g * 2 * EE;
    int src = eig[e], dst = eig[EE + e];
    d_norm[i] = ew[i] * d_deg_out[g * NN + src] * d_deg_in[g * NN + dst];
}

__global__ void transpose_whh_kernel(const float* __restrict__ Whh) {
    int i = blockIdx.x * blockDim.x + threadIdx.x;
    if (i < 512 * 128) {
        int j = i >> 7, k = i & 127;       // Whh[j][k]
        d_whhT[k * 512 + j] = Whh[i];
    }
}

// ---------------- edge aggregation (atomic scatter) -----------------------------
template<int FD>
__global__ void aggregate_kernel(const float* __restrict__ x, const int* __restrict__ ei) {
    long long idx = (long long)blockIdx.x * blockDim.x + threadIdx.x;
    if (idx >= (long long)Gn * EE * FD) return;
    int f  = (int)(idx & (FD - 1));
    int ge = (int)(idx / FD);
    int g = ge / EE, e = ge - g * EE;
    float w = d_norm[ge];
    const int* eig = ei + (size_t)g * 2 * EE;
    int src = eig[e], dst = eig[EE + e];
    const float* xg = x + (size_t)g * NN * FD;
    atomicAdd(&d_aggf[((size_t)g * NN + dst) * FD + f], w * xg[(size_t)src * FD + f]);
    atomicAdd(&d_aggb[((size_t)g * NN + src) * FD + f], w * xg[(size_t)dst * FD + f]);
}

// ---------------- tiled fp32 GEMM: C = s0*A0@W0^T + s1*A1@W1^T + bias ----------
// BM=64 rows, BN=128 cols, BK=16; 256 threads; thread = 8 rows x 4 cols.
template<int KD, bool DUAL>
__global__ void __launch_bounds__(256)
gemm_kernel(const float* __restrict__ A0, const float* __restrict__ A1,
            const float* __restrict__ W0, const float* __restrict__ W1,
            const float* __restrict__ b0, const float* __restrict__ b1,
            float* __restrict__ C, int M, int NC,
            float s0, float s1, float bs0, float bs1)
{
    __shared__ float As[16][68];
    __shared__ float Ws[16][132];
    const int tid = threadIdx.x;
    const int m0  = blockIdx.x * 64;
    const int jn  = blockIdx.y * 128;
    const int tc  = tid & 31;
    const int tr  = tid >> 5;

    float acc[8][4];
#pragma unroll
    for (int r = 0; r < 8; r++) { acc[r][0] = acc[r][1] = acc[r][2] = acc[r][3] = 0.f; }

    const int npass = DUAL ? 2 : 1;
    for (int pass = 0; pass < npass; pass++) {
        const float* A = pass ? A1 : A0;
        const float* W = pass ? W1 : W0;
        const float  s = pass ? s1 : s0;
        for (int kt = 0; kt < KD; kt += 16) {
            __syncthreads();
            {   // stage A tile (transposed k-major)
                int r = tid >> 2, k4 = (tid & 3) << 2;
                float4 v = *(const float4*)(A + (size_t)(m0 + r) * KD + kt + k4);
                As[k4 + 0][r] = v.x; As[k4 + 1][r] = v.y;
                As[k4 + 2][r] = v.z; As[k4 + 3][r] = v.w;
            }
#pragma unroll
            for (int it = 0; it < 2; it++) {   // stage W tile (transposed, pre-scaled)
                int j  = (tid >> 2) + it * 64;
                int k4 = (tid & 3) << 2;
                float4 v = make_float4(0.f, 0.f, 0.f, 0.f);
                if (jn + j < NC)
                    v = *(const float4*)(W + (size_t)(jn + j) * KD + kt + k4);
                Ws[k4 + 0][j] = v.x * s; Ws[k4 + 1][j] = v.y * s;
                Ws[k4 + 2][j] = v.z * s; Ws[k4 + 3][j] = v.w * s;
            }
            __syncthreads();
#pragma unroll
            for (int kk = 0; kk < 16; kk++) {
                float a[8];
                *(float4*)&a[0] = *(const float4*)&As[kk][tr * 8];
                *(float4*)&a[4] = *(const float4*)&As[kk][tr * 8 + 4];
                float4 w = *(const float4*)&Ws[kk][tc * 4];
#pragma unroll
                for (int r = 0; r < 8; r++) {
                    acc[r][0] += a[r] * w.x;
                    acc[r][1] += a[r] * w.y;
                    acc[r][2] += a[r] * w.z;
                    acc[r][3] += a[r] * w.w;
                }
            }
        }
    }

    int j = jn + tc * 4;
    if (j < NC) {
        float bias[4];
#pragma unroll
        for (int cidx = 0; cidx < 4; cidx++)
            bias[cidx] = bs0 * b0[j + cidx] + bs1 * b1[j + cidx];
#pragma unroll
        for (int r = 0; r < 8; r++) {
            int m = m0 + tr * 8 + r;
            float4 o;
            o.x = acc[r][0] + bias[0];
            o.y = acc[r][1] + bias[1];
            o.z = acc[r][2] + bias[2];
            o.w = acc[r][3] + bias[3];
            *(float4*)(C + (size_t)m * NC + j) = o;
        }
    }
}

// ---------------- LSTM recurrence: per-row independent, 32 rows/block -----------
__device__ __forceinline__ float sigmoidf_(float x) { return 1.f / (1.f + __expf(-x)); }

__global__ void __launch_bounds__(256)
lstm_kernel()
{
    __shared__ float h_s[32][128];
    __shared__ float w_s[16][512];
    const int tid  = threadIdx.x;
    const int tc   = tid & 31;   // 4 cols each (per gate)
    const int tr   = tid >> 5;   // 4 rows each
    const int row0 = blockIdx.x * 32 + tr * 4;

    float c[4][4];
#pragma unroll
    for (int a = 0; a < 4; a++)
#pragma unroll
        for (int b = 0; b < 4; b++) c[a][b] = 0.f;

    for (int t = 0; t < STEPS; t++) {
        float acc[4][4][4];   // [gate][row][col]
#pragma unroll
        for (int gate = 0; gate < 4; gate++)
#pragma unroll
            for (int ri = 0; ri < 4; ri++) {
                float4 v = *(const float4*)(d_gx +
                    ((size_t)(row0 + ri) * STEPS + t) * 512 + gate * 128 + tc * 4);
                acc[gate][ri][0] = v.x; acc[gate][ri][1] = v.y;
                acc[gate][ri][2] = v.z; acc[gate][ri][3] = v.w;
            }

        if (t > 0) {
            for (int kt = 0; kt < 8; kt++) {
                __syncthreads();
#pragma unroll
                for (int i = 0; i < 8; i++) {       // stage Whh^T tile [16][512]
                    int q  = tid + i * 256;
                    int kk = q >> 7;
                    int j4 = (q & 127) << 2;
                    *(float4*)&w_s[kk][j4] =
                        *(const float4*)(d_whhT + (size_t)(kt * 16 + kk) * 512 + j4);
                }
                __syncthreads();
#pragma unroll
                for (int kk = 0; kk < 16; kk++) {
                    float hv[4];
#pragma unroll
                    for (int ri = 0; ri < 4; ri++)
                        hv[ri] = h_s[tr * 4 + ri][kt * 16 + kk];
#pragma unroll
                    for (int gate = 0; gate < 4; gate++) {
                        float4 w = *(const float4*)&w_s[kk][gate * 128 + tc * 4];
#pragma unroll
                        for (int ri = 0; ri < 4; ri++) {
                            acc[gate][ri][0] += hv[ri] * w.x;
                            acc[gate][ri][1] += hv[ri] * w.y;
                            acc[gate][ri][2] += hv[ri] * w.z;
                            acc[gate][ri][3] += hv[ri] * w.w;
                        }
                    }
                }
            }
            __syncthreads();   // all reads of h_s done before overwrite below
        }

#pragma unroll
        for (int ri = 0; ri < 4; ri++) {
            float hn[4];
#pragma unroll
            for (int ci = 0; ci < 4; ci++) {
                float ig = sigmoidf_(acc[0][ri][ci]);
                float fg = sigmoidf_(acc[1][ri][ci]);
                float gg = tanhf(acc[2][ri][ci]);
                float og = sigmoidf_(acc[3][ri][ci]);
                float cn = fg * c[ri][ci] + ig * gg;
                c[ri][ci] = cn;
                hn[ci] = og * tanhf(cn);
            }
            float4 hv4 = make_float4(hn[0], hn[1], hn[2], hn[3]);
            *(float4*)&h_s[tr * 4 + ri][tc * 4] = hv4;
            if (t == STEPS - 1)
                *(float4*)(d_hlast + (size_t)(row0 + ri) * 128 + tc * 4) = hv4;
        }
        __syncthreads();
    }
}

// ---------------- launch --------------------------------------------------------
extern "C" void kernel_launch(void* const* d_in, const int* in_sizes, int n_in,
                              void* d_out, int out_size)
{
    const float* x_seq = (const float*)d_in[0];
    const int*   ei    = (const int*)  d_in[1];
    const float* ew    = (const float*)d_in[2];
    const float* W0s   = (const float*)d_in[3];
    const float* b0s   = (const float*)d_in[4];
    const float* W0d   = (const float*)d_in[5];
    const float* b0d   = (const float*)d_in[6];
    const float* W1s   = (const float*)d_in[7];
    const float* b1s   = (const float*)d_in[8];
    const float* W1d   = (const float*)d_in[9];
    const float* b1d   = (const float*)d_in[10];
    const float* Wih   = (const float*)d_in[11];
    const float* Whh   = (const float*)d_in[12];
    const float* bih   = (const float*)d_in[13];
    const float* bhh   = (const float*)d_in[14];
    const float* Wp    = (const float*)d_in[15];
    const float* bp    = (const float*)d_in[16];
    float* out = (float*)d_out;

    float *aggf, *aggb, *h0, *h1, *gx, *hlast;
    cudaGetSymbolAddress((void**)&aggf,  d_aggf);
    cudaGetSymbolAddress((void**)&aggb,  d_aggb);
    cudaGetSymbolAddress((void**)&h0,    d_h0);
    cudaGetSymbolAddress((void**)&h1,    d_h1);
    cudaGetSymbolAddress((void**)&gx,    d_gx);
    cudaGetSymbolAddress((void**)&hlast, d_hlast);

    const int M = Gn * NN;   // 128000

    // ---- degrees + edge norms ----
    zero_deg_kernel<<<(Gn * NN + 255) / 256, 256>>>();
    degree_kernel<<<(Gn * EE + 255) / 256, 256>>>(ei, ew);
    inv_kernel<<<(Gn * NN + 255) / 256, 256>>>();
    norm_kernel<<<(Gn * EE + 255) / 256, 256>>>(ei, ew);

    // ---- GCN layer 0 (F=64 -> H=128) ----
    zero_agg_kernel<<<(Gn * NN * FD0 / 4 + 255) / 256, 256>>>(Gn * NN * FD0 / 4);
    aggregate_kernel<64><<<(int)(((long long)Gn * EE * 64) / 256), 256>>>(x_seq, ei);
    gemm_kernel<64, true><<<dim3(M / 64, 1), 256>>>(
        aggf, aggb, W0s, W0d, b0s, b0d, h0, M, HD, 0.5f, 0.5f, 0.5f, 0.5f);

    // ---- GCN layer 1 (H=128 -> H=128) ----
    zero_agg_kernel<<<(Gn * NN * HD / 4 + 255) / 256, 256>>>(Gn * NN * HD / 4);
    aggregate_kernel<128><<<(int)(((long long)Gn * EE * 128) / 256), 256>>>(h0, ei);
    gemm_kernel<128, true><<<dim3(M / 64, 1), 256>>>(
        aggf, aggb, W1s, W1d, b1s, b1d, h1, M, HD, 0.5f, 0.5f, 0.5f, 0.5f);

    // ---- LSTM: precompute x@Wih.T + bih + bhh for all rows/steps ----
    transpose_whh_kernel<<<(512 * 128 + 255) / 256, 256>>>(Whh);
    gemm_kernel<128, false><<<dim3(M / 64, 4), 256>>>(
        h1, nullptr, Wih, nullptr, bih, bhh, gx, M, 4 * HD, 1.f, 0.f, 1.f, 1.f);

    // ---- LSTM recurrence (per-row independent; 8 steps inside one kernel) ----
    lstm_kernel<<<BNR / 32, 256>>>();

    // ---- final projection [16000,128] @ Wp^T -> [16000,64] == [B,N,64] ----
    gemm_kernel<128, false><<<dim3(BNR / 64, 1), 256>>>(
        hlast, nullptr, Wp, nullptr, bp, bp, out, BNR, FD0, 1.f, 0.f, 1.f, 0.f);
}

// round 2
// speedup vs baseline: 1.2977x; 1.2977x over previous
#include <cuda_runtime.h>

// Problem dims (fixed by the reference)
#define Gn   32          // B*S graphs
#define NN   4000        // nodes
#define EE   32000       // edges per graph
#define FD0  64          // input feature dim
#define HD   128         // hidden dim
#define BNR  16000       // B*N LSTM rows
#define STEPS 8

// ---------------- scratch (device globals; no allocations allowed) -------------
__device__ float d_deg_out[Gn * NN];   // weighted out-degree -> inv sqrt
__device__ float d_deg_in [Gn * NN];
__device__ int   d_cnt_f[Gn * NN];     // edge counts by dst (forward CSR)
__device__ int   d_cnt_b[Gn * NN];     // edge counts by src (backward CSR)
__device__ int   d_off_f[Gn * NN];
__device__ int   d_off_b[Gn * NN];
__device__ int   d_cur_f[Gn * NN];
__device__ int   d_cur_b[Gn * NN];
__device__ int   d_csr_if[Gn * EE];    // forward: neighbor = src, listed per dst
__device__ float d_csr_wf[Gn * EE];
__device__ int   d_csr_ib[Gn * EE];    // backward: neighbor = dst, listed per src
__device__ float d_csr_wb[Gn * EE];
__device__ float d_aggf  [(size_t)Gn * NN * HD];
__device__ float d_aggb  [(size_t)Gn * NN * HD];
__device__ float d_h0    [(size_t)Gn * NN * HD];
__device__ float d_h1    [(size_t)Gn * NN * HD];
__device__ float d_gx    [(size_t)BNR * STEPS * 4 * HD];
__device__ float d_hlast [(size_t)BNR * HD];
__device__ float d_whhT  [HD * 4 * HD];

// ---------------- CSR build ------------------------------------------------------
__global__ void zero_kernel() {
    int i = blockIdx.x * blockDim.x + threadIdx.x;
    if (i < Gn * NN) {
        d_deg_out[i] = 0.f; d_deg_in[i] = 0.f;
        d_cnt_f[i] = 0;     d_cnt_b[i] = 0;
    }
}

__global__ void degcnt_kernel(const int* __restrict__ ei, const float* __restrict__ ew) {
    int i = blockIdx.x * blockDim.x + threadIdx.x;
    if (i >= Gn * EE) return;
    int g = i / EE, e = i - g * EE;
    const int* eig = ei + (size_t)g * 2 * EE;
    int src = eig[e], dst = eig[EE + e];
    float w = ew[i];
    atomicAdd(&d_deg_out[g * NN + src], w);
    atomicAdd(&d_deg_in [g * NN + dst], w);
    atomicAdd(&d_cnt_f[g * NN + dst], 1);
    atomicAdd(&d_cnt_b[g * NN + src], 1);
}

__global__ void inv_kernel() {
    int i = blockIdx.x * blockDim.x + threadIdx.x;
    if (i >= Gn * NN) return;
    float v = d_deg_out[i];
    d_deg_out[i] = (v > 0.f) ? rsqrtf(fmaxf(v, 1e-12f)) : 0.f;
    v = d_deg_in[i];
    d_deg_in[i]  = (v > 0.f) ? rsqrtf(fmaxf(v, 1e-12f)) : 0.f;
}

// per-(graph, dir) exclusive scan of 4000 counts; 1024 threads x 4 elems
__global__ void __launch_bounds__(1024) scan_kernel() {
    int g   = blockIdx.x;
    int dir = blockIdx.y;
    const int* cnt = dir ? d_cnt_b : d_cnt_f;
    int* off = dir ? d_off_b : d_off_f;
    int* cur = dir ? d_cur_b : d_cur_f;
    int tid = threadIdx.x;
    int base = g * NN;
    int v[4], tot = 0;
#pragma unroll
    for (int k = 0; k < 4; k++) {
        int i = tid * 4 + k;
        v[k] = (i < NN) ? cnt[base + i] : 0;
        tot += v[k];
    }
    __shared__ int s[1024];
    s[tid] = tot;
    __syncthreads();
    for (int d = 1; d < 1024; d <<= 1) {
        int t = (tid >= d) ? s[tid - d] : 0;
        __syncthreads();
        s[tid] += t;
        __syncthreads();
    }
    int ex = s[tid] - tot;   // exclusive prefix of this thread's chunk
#pragma unroll
    for (int k = 0; k < 4; k++) {
        int i = tid * 4 + k;
        if (i < NN) { off[base + i] = ex; cur[base + i] = ex; ex += v[k]; }
    }
}

__global__ void scatter_kernel(const int* __restrict__ ei, const float* __restrict__ ew) {
    int i = blockIdx.x * blockDim.x + threadIdx.x;
    if (i >= Gn * EE) return;
    int g = i / EE, e = i - g * EE;
    const int* eig = ei + (size_t)g * 2 * EE;
    int src = eig[e], dst = eig[EE + e];
    float w = ew[i] * d_deg_out[g * NN + src] * d_deg_in[g * NN + dst];
    int pf = atomicAdd(&d_cur_f[g * NN + dst], 1);
    d_csr_if[g * EE + pf] = src;
    d_csr_wf[g * EE + pf] = w;
    int pb = atomicAdd(&d_cur_b[g * NN + src], 1);
    d_csr_ib[g * EE + pb] = dst;
    d_csr_wb[g * EE + pb] = w;
}

// ---------------- gather aggregation: one warp per (node, dir), no atomics -------
template<int FD>
__global__ void __launch_bounds__(256) gather_kernel(const float* __restrict__ x) {
    int gw = (blockIdx.x * 256 + threadIdx.x) >> 5;
    int lane = threadIdx.x & 31;
    if (gw >= Gn * NN * 2) return;
    int dir = gw & 1;
    int gn  = gw >> 1;            // g*NN + n
    int g   = gn / NN;
    const int*   off = dir ? d_off_b : d_off_f;
    const int*   cnt = dir ? d_cnt_b : d_cnt_f;
    const int*   nb  = dir ? d_csr_ib : d_csr_if;
    const float* wv  = dir ? d_csr_wb : d_csr_wf;
    float* outp      = dir ? d_aggb   : d_aggf;
    int o = off[gn], c = cnt[gn];
    const float* xg = x + (size_t)g * NN * FD;
    const int ebase = g * EE + o;

    if (FD == 128) {
        float4 acc = make_float4(0.f, 0.f, 0.f, 0.f);
        for (int j = 0; j < c; j++) {
            int   s = nb[ebase + j];
            float w = wv[ebase + j];
            float4 xv = *(const float4*)(xg + (size_t)s * FD + lane * 4);
            acc.x += w * xv.x; acc.y += w * xv.y;
            acc.z += w * xv.z; acc.w += w * xv.w;
        }
        *(float4*)(outp + (size_t)gn * FD + lane * 4) = acc;
    } else {
        float2 acc = make_float2(0.f, 0.f);
        for (int j = 0; j < c; j++) {
            int   s = nb[ebase + j];
            float w = wv[ebase + j];
            float2 xv = *(const float2*)(xg + (size_t)s * FD + lane * 2);
            acc.x += w * xv.x; acc.y += w * xv.y;
        }
        *(float2*)(outp + (size_t)gn * FD + lane * 2) = acc;
    }
}

// ---------------- tiled fp32 GEMM: C = s0*A0@W0^T + s1*A1@W1^T + bias ----------
template<int KD, bool DUAL>
__global__ void __launch_bounds__(256)
gemm_kernel(const float* __restrict__ A0, const float* __restrict__ A1,
            const float* __restrict__ W0, const float* __restrict__ W1,
            const float* __restrict__ b0, const float* __restrict__ b1,
            float* __restrict__ C, int M, int NC,
            float s0, float s1, float bs0, float bs1)
{
    __shared__ float As[16][68];
    __shared__ float Ws[16][132];
    const int tid = threadIdx.x;
    const int m0  = blockIdx.x * 64;
    const int jn  = blockIdx.y * 128;
    const int tc  = tid & 31;
    const int tr  = tid >> 5;

    float acc[8][4];
#pragma unroll
    for (int r = 0; r < 8; r++) { acc[r][0] = acc[r][1] = acc[r][2] = acc[r][3] = 0.f; }

    const int npass = DUAL ? 2 : 1;
    for (int pass = 0; pass < npass; pass++) {
        const float* A = pass ? A1 : A0;
        const float* W = pass ? W1 : W0;
        const float  s = pass ? s1 : s0;
        for (int kt = 0; kt < KD; kt += 16) {
            __syncthreads();
            {
                int r = tid >> 2, k4 = (tid & 3) << 2;
                float4 v = *(const float4*)(A + (size_t)(m0 + r) * KD + kt + k4);
                As[k4 + 0][r] = v.x; As[k4 + 1][r] = v.y;
                As[k4 + 2][r] = v.z; As[k4 + 3][r] = v.w;
            }
#pragma unroll
            for (int it = 0; it < 2; it++) {
                int j  = (tid >> 2) + it * 64;
                int k4 = (tid & 3) << 2;
                float4 v = make_float4(0.f, 0.f, 0.f, 0.f);
                if (jn + j < NC)
                    v = *(const float4*)(W + (size_t)(jn + j) * KD + kt + k4);
                Ws[k4 + 0][j] = v.x * s; Ws[k4 + 1][j] = v.y * s;
                Ws[k4 + 2][j] = v.z * s; Ws[k4 + 3][j] = v.w * s;
            }
            __syncthreads();
#pragma unroll
            for (int kk = 0; kk < 16; kk++) {
                float a[8];
                *(float4*)&a[0] = *(const float4*)&As[kk][tr * 8];
                *(float4*)&a[4] = *(const float4*)&As[kk][tr * 8 + 4];
                float4 w = *(const float4*)&Ws[kk][tc * 4];
#pragma unroll
                for (int r = 0; r < 8; r++) {
                    acc[r][0] += a[r] * w.x;
                    acc[r][1] += a[r] * w.y;
                    acc[r][2] += a[r] * w.z;
                    acc[r][3] += a[r] * w.w;
                }
            }
        }
    }

    int j = jn + tc * 4;
    if (j < NC) {
        float bias[4];
#pragma unroll
        for (int cidx = 0; cidx < 4; cidx++)
            bias[cidx] = bs0 * b0[j + cidx] + bs1 * b1[j + cidx];
#pragma unroll
        for (int r = 0; r < 8; r++) {
            int m = m0 + tr * 8 + r;
            float4 o;
            o.x = acc[r][0] + bias[0];
            o.y = acc[r][1] + bias[1];
            o.z = acc[r][2] + bias[2];
            o.w = acc[r][3] + bias[3];
            *(float4*)(C + (size_t)m * NC + j) = o;
        }
    }
}

__global__ void transpose_whh_kernel(const float* __restrict__ Whh) {
    int i = blockIdx.x * blockDim.x + threadIdx.x;
    if (i < 512 * 128) {
        int j = i >> 7, k = i & 127;
        d_whhT[k * 512 + j] = Whh[i];
    }
}

// ---------------- LSTM recurrence: per-row independent, 32 rows/block -----------
__device__ __forceinline__ float sigmoidf_(float x) { return 1.f / (1.f + __expf(-x)); }

__global__ void __launch_bounds__(256)
lstm_kernel()
{
    __shared__ float h_s[32][128];
    __shared__ float w_s[16][512];
    const int tid  = threadIdx.x;
    const int tc   = tid & 31;
    const int tr   = tid >> 5;
    const int row0 = blockIdx.x * 32 + tr * 4;

    float c[4][4];
#pragma unroll
    for (int a = 0; a < 4; a++)
#pragma unroll
        for (int b = 0; b < 4; b++) c[a][b] = 0.f;

    for (int t = 0; t < STEPS; t++) {
        float acc[4][4][4];
#pragma unroll
        for (int gate = 0; gate < 4; gate++)
#pragma unroll
            for (int ri = 0; ri < 4; ri++) {
                float4 v = *(const float4*)(d_gx +
                    ((size_t)(row0 + ri) * STEPS + t) * 512 + gate * 128 + tc * 4);
                acc[gate][ri][0] = v.x; acc[gate][ri][1] = v.y;
                acc[gate][ri][2] = v.z; acc[gate][ri][3] = v.w;
            }

        if (t > 0) {
            for (int kt = 0; kt < 8; kt++) {
                __syncthreads();
#pragma unroll
                for (int i = 0; i < 8; i++) {
                    int q  = tid + i * 256;
                    int kk = q >> 7;
                    int j4 = (q & 127) << 2;
                    *(float4*)&w_s[kk][j4] =
                        *(const float4*)(d_whhT + (size_t)(kt * 16 + kk) * 512 + j4);
                }
                __syncthreads();
#pragma unroll
                for (int kk = 0; kk < 16; kk++) {
                    float hv[4];
#pragma unroll
                    for (int ri = 0; ri < 4; ri++)
                        hv[ri] = h_s[tr * 4 + ri][kt * 16 + kk];
#pragma unroll
                    for (int gate = 0; gate < 4; gate++) {
                        float4 w = *(const float4*)&w_s[kk][gate * 128 + tc * 4];
#pragma unroll
                        for (int ri = 0; ri < 4; ri++) {
                            acc[gate][ri][0] += hv[ri] * w.x;
                            acc[gate][ri][1] += hv[ri] * w.y;
                            acc[gate][ri][2] += hv[ri] * w.z;
                            acc[gate][ri][3] += hv[ri] * w.w;
                        }
                    }
                }
            }
            __syncthreads();
        }

#pragma unroll
        for (int ri = 0; ri < 4; ri++) {
            float hn[4];
#pragma unroll
            for (int ci = 0; ci < 4; ci++) {
                float ig = sigmoidf_(acc[0][ri][ci]);
                float fg = sigmoidf_(acc[1][ri][ci]);
                float gg = tanhf(acc[2][ri][ci]);
                float og = sigmoidf_(acc[3][ri][ci]);
                float cn = fg * c[ri][ci] + ig * gg;
                c[ri][ci] = cn;
                hn[ci] = og * tanhf(cn);
            }
            float4 hv4 = make_float4(hn[0], hn[1], hn[2], hn[3]);
            *(float4*)&h_s[tr * 4 + ri][tc * 4] = hv4;
            if (t == STEPS - 1)
                *(float4*)(d_hlast + (size_t)(row0 + ri) * 128 + tc * 4) = hv4;
        }
        __syncthreads();
    }
}

// ---------------- launch --------------------------------------------------------
extern "C" void kernel_launch(void* const* d_in, const int* in_sizes, int n_in,
                              void* d_out, int out_size)
{
    const float* x_seq = (const float*)d_in[0];
    const int*   ei    = (const int*)  d_in[1];
    const float* ew    = (const float*)d_in[2];
    const float* W0s   = (const float*)d_in[3];
    const float* b0s   = (const float*)d_in[4];
    const float* W0d   = (const float*)d_in[5];
    const float* b0d   = (const float*)d_in[6];
    const float* W1s   = (const float*)d_in[7];
    const float* b1s   = (const float*)d_in[8];
    const float* W1d   = (const float*)d_in[9];
    const float* b1d   = (const float*)d_in[10];
    const float* Wih   = (const float*)d_in[11];
    const float* Whh   = (const float*)d_in[12];
    const float* bih   = (const float*)d_in[13];
    const float* bhh   = (const float*)d_in[14];
    const float* Wp    = (const float*)d_in[15];
    const float* bp    = (const float*)d_in[16];
    float* out = (float*)d_out;

    float *aggf, *aggb, *h0, *h1, *gx, *hlast;
    cudaGetSymbolAddress((void**)&aggf,  d_aggf);
    cudaGetSymbolAddress((void**)&aggb,  d_aggb);
    cudaGetSymbolAddress((void**)&h0,    d_h0);
    cudaGetSymbolAddress((void**)&h1,    d_h1);
    cudaGetSymbolAddress((void**)&gx,    d_gx);
    cudaGetSymbolAddress((void**)&hlast, d_hlast);

    const int M = Gn * NN;   // 128000

    // ---- CSR build (both directions) ----
    zero_kernel<<<(Gn * NN + 255) / 256, 256>>>();
    degcnt_kernel<<<(Gn * EE + 255) / 256, 256>>>(ei, ew);
    inv_kernel<<<(Gn * NN + 255) / 256, 256>>>();
    scan_kernel<<<dim3(Gn, 2), 1024>>>();
    scatter_kernel<<<(Gn * EE + 255) / 256, 256>>>(ei, ew);

    const int gblocks = (Gn * NN * 2 * 32 + 255) / 256;

    // ---- GCN layer 0 (F=64 -> H=128): gather + dual GEMM ----
    gather_kernel<64><<<gblocks, 256>>>(x_seq);
    gemm_kernel<64, true><<<dim3(M / 64, 1), 256>>>(
        aggf, aggb, W0s, W0d, b0s, b0d, h0, M, HD, 0.5f, 0.5f, 0.5f, 0.5f);

    // ---- GCN layer 1 (H=128 -> H=128) ----
    gather_kernel<128><<<gblocks, 256>>>(h0);
    gemm_kernel<128, true><<<dim3(M / 64, 1), 256>>>(
        aggf, aggb, W1s, W1d, b1s, b1d, h1, M, HD, 0.5f, 0.5f, 0.5f, 0.5f);

    // ---- LSTM input GEMM: x@Wih.T + bih + bhh for all rows/steps ----
    transpose_whh_kernel<<<(512 * 128 + 255) / 256, 256>>>(Whh);
    gemm_kernel<128, false><<<dim3(M / 64, 4), 256>>>(
        h1, nullptr, Wih, nullptr, bih, bhh, gx, M, 4 * HD, 1.f, 0.f, 1.f, 1.f);

    // ---- LSTM recurrence ----
    lstm_kernel<<<BNR / 32, 256>>>();

    // ---- final projection [16000,128] @ Wp^T -> [B,N,64] ----
    gemm_kernel<128, false><<<dim3(BNR / 64, 1), 256>>>(
        hlast, nullptr, Wp, nullptr, bp, bp, out, BNR, FD0, 1.f, 0.f, 1.f, 0.f);
}

// round 3
// speedup vs baseline: 1.3455x; 1.0369x over previous
#include <cuda_runtime.h>

// Problem dims (fixed by the reference)
#define Gn   32
#define NN   4000
#define EE   32000
#define FD0  64
#define HD   128
#define BNR  16000
#define STEPS 8

typedef unsigned long long u64;

__device__ __forceinline__ u64 fma2(u64 a, u64 b, u64 c) {
    u64 d;
    asm("fma.rn.f32x2 %0, %1, %2, %3;" : "=l"(d) : "l"(a), "l"(b), "l"(c));
    return d;
}
__device__ __forceinline__ u64 pack2(float x) {
    u64 d; asm("mov.b64 %0, {%1, %1};" : "=l"(d) : "f"(x)); return d;
}

// ---------------- scratch (device globals) --------------------------------------
__device__ float d_deg_out[Gn * NN];
__device__ float d_deg_in [Gn * NN];
__device__ int   d_cnt_f[Gn * NN];
__device__ int   d_cnt_b[Gn * NN];
__device__ int   d_off_f[Gn * NN];
__device__ int   d_off_b[Gn * NN];
__device__ int   d_cur_f[Gn * NN];
__device__ int   d_cur_b[Gn * NN];
__device__ int   d_csr_if[Gn * EE];
__device__ float d_csr_wf[Gn * EE];
__device__ int   d_csr_ib[Gn * EE];
__device__ float d_csr_wb[Gn * EE];
__device__ float d_aggf  [(size_t)Gn * NN * HD];
__device__ float d_aggb  [(size_t)Gn * NN * HD];
__device__ float d_h0    [(size_t)Gn * NN * HD];
__device__ float d_h1    [(size_t)Gn * NN * HD];
__device__ float d_gx    [(size_t)BNR * STEPS * 4 * HD];
__device__ float d_hlast [(size_t)BNR * HD];
__device__ float d_whhT  [HD * 4 * HD];

// ---------------- CSR build ------------------------------------------------------
__global__ void zero_kernel() {
    int i = blockIdx.x * blockDim.x + threadIdx.x;
    if (i < Gn * NN) {
        d_deg_out[i] = 0.f; d_deg_in[i] = 0.f;
        d_cnt_f[i] = 0;     d_cnt_b[i] = 0;
    }
}

__global__ void degcnt_kernel(const int* __restrict__ ei, const float* __restrict__ ew) {
    int i = blockIdx.x * blockDim.x + threadIdx.x;
    if (i >= Gn * EE) return;
    int g = i / EE, e = i - g * EE;
    const int* eig = ei + (size_t)g * 2 * EE;
    int src = eig[e], dst = eig[EE + e];
    float w = ew[i];
    atomicAdd(&d_deg_out[g * NN + src], w);
    atomicAdd(&d_deg_in [g * NN + dst], w);
    atomicAdd(&d_cnt_f[g * NN + dst], 1);
    atomicAdd(&d_cnt_b[g * NN + src], 1);
}

__global__ void inv_kernel() {
    int i = blockIdx.x * blockDim.x + threadIdx.x;
    if (i >= Gn * NN) return;
    float v = d_deg_out[i];
    d_deg_out[i] = (v > 0.f) ? rsqrtf(fmaxf(v, 1e-12f)) : 0.f;
    v = d_deg_in[i];
    d_deg_in[i]  = (v > 0.f) ? rsqrtf(fmaxf(v, 1e-12f)) : 0.f;
}

__global__ void __launch_bounds__(1024) scan_kernel() {
    int g   = blockIdx.x;
    int dir = blockIdx.y;
    const int* cnt = dir ? d_cnt_b : d_cnt_f;
    int* off = dir ? d_off_b : d_off_f;
    int* cur = dir ? d_cur_b : d_cur_f;
    int tid = threadIdx.x;
    int base = g * NN;
    int v[4], tot = 0;
#pragma unroll
    for (int k = 0; k < 4; k++) {
        int i = tid * 4 + k;
        v[k] = (i < NN) ? cnt[base + i] : 0;
        tot += v[k];
    }
    __shared__ int s[1024];
    s[tid] = tot;
    __syncthreads();
    for (int d = 1; d < 1024; d <<= 1) {
        int t = (tid >= d) ? s[tid - d] : 0;
        __syncthreads();
        s[tid] += t;
        __syncthreads();
    }
    int ex = s[tid] - tot;
#pragma unroll
    for (int k = 0; k < 4; k++) {
        int i = tid * 4 + k;
        if (i < NN) { off[base + i] = ex; cur[base + i] = ex; ex += v[k]; }
    }
}

__global__ void scatter_kernel(const int* __restrict__ ei, const float* __restrict__ ew) {
    int i = blockIdx.x * blockDim.x + threadIdx.x;
    if (i >= Gn * EE) return;
    int g = i / EE, e = i - g * EE;
    const int* eig = ei + (size_t)g * 2 * EE;
    int src = eig[e], dst = eig[EE + e];
    float w = ew[i] * d_deg_out[g * NN + src] * d_deg_in[g * NN + dst];
    int pf = atomicAdd(&d_cur_f[g * NN + dst], 1);
    d_csr_if[g * EE + pf] = src;
    d_csr_wf[g * EE + pf] = w;
    int pb = atomicAdd(&d_cur_b[g * NN + src], 1);
    d_csr_ib[g * EE + pb] = dst;
    d_csr_wb[g * EE + pb] = w;
}

// ---------------- gather aggregation: one warp per (node, dir) -------------------
template<int FD>
__global__ void __launch_bounds__(256) gather_kernel(const float* __restrict__ x) {
    int gw = (blockIdx.x * 256 + threadIdx.x) >> 5;
    int lane = threadIdx.x & 31;
    if (gw >= Gn * NN * 2) return;
    int dir = gw & 1;
    int gn  = gw >> 1;
    int g   = gn / NN;
    const int*   off = dir ? d_off_b : d_off_f;
    const int*   cnt = dir ? d_cnt_b : d_cnt_f;
    const int*   nb  = dir ? d_csr_ib : d_csr_if;
    const float* wv  = dir ? d_csr_wb : d_csr_wf;
    float* outp      = dir ? d_aggb   : d_aggf;
    int o = off[gn], c = cnt[gn];
    const float* xg = x + (size_t)g * NN * FD;
    const int ebase = g * EE + o;

    if (FD == 128) {
        float4 acc = make_float4(0.f, 0.f, 0.f, 0.f);
        for (int j = 0; j < c; j++) {
            int   s = nb[ebase + j];
            float w = wv[ebase + j];
            float4 xv = *(const float4*)(xg + (size_t)s * FD + lane * 4);
            acc.x += w * xv.x; acc.y += w * xv.y;
            acc.z += w * xv.z; acc.w += w * xv.w;
        }
        *(float4*)(outp + (size_t)gn * FD + lane * 4) = acc;
    } else {
        float2 acc = make_float2(0.f, 0.f);
        for (int j = 0; j < c; j++) {
            int   s = nb[ebase + j];
            float w = wv[ebase + j];
            float2 xv = *(const float2*)(xg + (size_t)s * FD + lane * 2);
            acc.x += w * xv.x; acc.y += w * xv.y;
        }
        *(float2*)(outp + (size_t)gn * FD + lane * 2) = acc;
    }
}

// ---------------- FMA2 GEMM: 128x128 block tile, 8x8/thread ---------------------
// C[M,NC] = s0*A0@W0^T + s1*A1@W1^T + bs0*b0 + bs1*b1. NC multiple of 128.
template<int KD, bool DUAL>
__global__ void __launch_bounds__(256)
gemm2_kernel(const float* __restrict__ A0, const float* __restrict__ A1,
             const float* __restrict__ W0, const float* __restrict__ W1,
             const float* __restrict__ b0, const float* __restrict__ b1,
             float* __restrict__ C, int M, int NC,
             float s0, float s1, float bs0, float bs1)
{
    __shared__ float As[16][132];
    __shared__ float Ws[16][132];
    const int tid = threadIdx.x;
    const int m0  = blockIdx.x * 128;
    const int jn  = blockIdx.y * 128;
    const int ty  = tid >> 4;        // 0..15 -> rows ty*8
    const int tx  = tid & 15;        // 0..15 -> cols tx*8

    u64 acc[8][4];
#pragma unroll
    for (int r = 0; r < 8; r++)
#pragma unroll
        for (int cidx = 0; cidx < 4; cidx++) acc[r][cidx] = 0ull;

    const int npass = DUAL ? 2 : 1;
    for (int pass = 0; pass < npass; pass++) {
        const float* A = pass ? A1 : A0;
        const float* W = pass ? W1 : W0;
        const float  s = pass ? s1 : s0;
        for (int kt = 0; kt < KD; kt += 16) {
            __syncthreads();
#pragma unroll
            for (int half = 0; half < 2; half++) {   // stage A tile transposed
                int r  = (tid >> 2) + half * 64;
                int k4 = (tid & 3) << 2;
                float4 v = *(const float4*)(A + (size_t)(m0 + r) * KD + kt + k4);
                As[k4 + 0][r] = v.x; As[k4 + 1][r] = v.y;
                As[k4 + 2][r] = v.z; As[k4 + 3][r] = v.w;
            }
#pragma unroll
            for (int half = 0; half < 2; half++) {   // stage W tile transposed+scaled
                int j  = (tid >> 2) + half * 64;
                int k4 = (tid & 3) << 2;
                float4 v = *(const float4*)(W + (size_t)(jn + j) * KD + kt + k4);
                Ws[k4 + 0][j] = v.x * s; Ws[k4 + 1][j] = v.y * s;
                Ws[k4 + 2][j] = v.z * s; Ws[k4 + 3][j] = v.w * s;
            }
            __syncthreads();
#pragma unroll
            for (int kk = 0; kk < 16; kk++) {
                float a[8];
                *(float4*)&a[0] = *(const float4*)&As[kk][ty * 8];
                *(float4*)&a[4] = *(const float4*)&As[kk][ty * 8 + 4];
                float4 wA = *(const float4*)&Ws[kk][tx * 8];
                float4 wB = *(const float4*)&Ws[kk][tx * 8 + 4];
                u64 w01 = *(const u64*)&wA.x;
                u64 w23 = *(const u64*)&wA.z;
                u64 w45 = *(const u64*)&wB.x;
                u64 w67 = *(const u64*)&wB.z;
#pragma unroll
                for (int r = 0; r < 8; r++) {
                    u64 aa = pack2(a[r]);
                    acc[r][0] = fma2(aa, w01, acc[r][0]);
                    acc[r][1] = fma2(aa, w23, acc[r][1]);
                    acc[r][2] = fma2(aa, w45, acc[r][2]);
                    acc[r][3] = fma2(aa, w67, acc[r][3]);
                }
            }
        }
    }

    int j = jn + tx * 8;
    float bias[8];
#pragma unroll
    for (int cidx = 0; cidx < 8; cidx++)
        bias[cidx] = bs0 * b0[j + cidx] + bs1 * b1[j + cidx];
#pragma unroll
    for (int r = 0; r < 8; r++) {
        int m = m0 + ty * 8 + r;
        float2 p0 = *(float2*)&acc[r][0];
        float2 p1 = *(float2*)&acc[r][1];
        float2 p2 = *(float2*)&acc[r][2];
        float2 p3 = *(float2*)&acc[r][3];
        float4 o0 = make_float4(p0.x + bias[0], p0.y + bias[1], p1.x + bias[2], p1.y + bias[3]);
        float4 o1 = make_float4(p2.x + bias[4], p2.y + bias[5], p3.x + bias[6], p3.y + bias[7]);
        *(float4*)(C + (size_t)m * NC + j)     = o0;
        *(float4*)(C + (size_t)m * NC + j + 4) = o1;
    }
}

// ---------------- small 64x128 GEMM (projection only, NC=64) --------------------
template<int KD>
__global__ void __launch_bounds__(256)
gemm_small_kernel(const float* __restrict__ A0,
                  const float* __restrict__ W0, const float* __restrict__ b0,
                  float* __restrict__ C, int M, int NC)
{
    __shared__ float As[16][68];
    __shared__ float Ws[16][132];
    const int tid = threadIdx.x;
    const int m0  = blockIdx.x * 64;
    const int tc  = tid & 31;
    const int tr  = tid >> 5;

    float acc[8][4];
#pragma unroll
    for (int r = 0; r < 8; r++) { acc[r][0] = acc[r][1] = acc[r][2] = acc[r][3] = 0.f; }

    for (int kt = 0; kt < KD; kt += 16) {
        __syncthreads();
        {
            int r = tid >> 2, k4 = (tid & 3) << 2;
            float4 v = *(const float4*)(A0 + (size_t)(m0 + r) * KD + kt + k4);
            As[k4 + 0][r] = v.x; As[k4 + 1][r] = v.y;
            As[k4 + 2][r] = v.z; As[k4 + 3][r] = v.w;
        }
#pragma unroll
        for (int it = 0; it < 2; it++) {
            int j  = (tid >> 2) + it * 64;
            int k4 = (tid & 3) << 2;
            float4 v = make_float4(0.f, 0.f, 0.f, 0.f);
            if (j < NC)
                v = *(const float4*)(W0 + (size_t)j * KD + kt + k4);
            Ws[k4 + 0][j] = v.x; Ws[k4 + 1][j] = v.y;
            Ws[k4 + 2][j] = v.z; Ws[k4 + 3][j] = v.w;
        }
        __syncthreads();
#pragma unroll
        for (int kk = 0; kk < 16; kk++) {
            float a[8];
            *(float4*)&a[0] = *(const float4*)&As[kk][tr * 8];
            *(float4*)&a[4] = *(const float4*)&As[kk][tr * 8 + 4];
            float4 w = *(const float4*)&Ws[kk][tc * 4];
#pragma unroll
            for (int r = 0; r < 8; r++) {
                acc[r][0] += a[r] * w.x;
                acc[r][1] += a[r] * w.y;
                acc[r][2] += a[r] * w.z;
                acc[r][3] += a[r] * w.w;
            }
        }
    }

    int j = tc * 4;
    if (j < NC) {
        float4 bias = *(const float4*)(b0 + j);
#pragma unroll
        for (int r = 0; r < 8; r++) {
            int m = m0 + tr * 8 + r;
            float4 o;
            o.x = acc[r][0] + bias.x;
            o.y = acc[r][1] + bias.y;
            o.z = acc[r][2] + bias.z;
            o.w = acc[r][3] + bias.w;
            *(float4*)(C + (size_t)m * NC + j) = o;
        }
    }
}

__global__ void transpose_whh_kernel(const float* __restrict__ Whh) {
    int i = blockIdx.x * blockDim.x + threadIdx.x;
    if (i < 512 * 128) {
        int j = i >> 7, k = i & 127;
        d_whhT[k * 512 + j] = Whh[i];
    }
}

// ---------------- LSTM recurrence with FMA2 -------------------------------------
__device__ __forceinline__ float sigmoidf_(float x) { return 1.f / (1.f + __expf(-x)); }

__global__ void __launch_bounds__(256)
lstm_kernel()
{
    __shared__ float h_s[32][128];
    __shared__ float w_s[16][512];
    const int tid  = threadIdx.x;
    const int tc   = tid & 31;
    const int tr   = tid >> 5;
    const int row0 = blockIdx.x * 32 + tr * 4;

    float c[4][4];
#pragma unroll
    for (int a = 0; a < 4; a++)
#pragma unroll
        for (int b = 0; b < 4; b++) c[a][b] = 0.f;

    for (int t = 0; t < STEPS; t++) {
        u64 acc[4][4][2];   // [gate][row][colpair]
#pragma unroll
        for (int gate = 0; gate < 4; gate++)
#pragma unroll
            for (int ri = 0; ri < 4; ri++) {
                float4 v = *(const float4*)(d_gx +
                    ((size_t)(row0 + ri) * STEPS + t) * 512 + gate * 128 + tc * 4);
                acc[gate][ri][0] = *(const u64*)&v.x;
                acc[gate][ri][1] = *(const u64*)&v.z;
            }

        if (t > 0) {
            for (int kt = 0; kt < 8; kt++) {
                __syncthreads();
#pragma unroll
                for (int i = 0; i < 8; i++) {
                    int q  = tid + i * 256;
                    int kk = q >> 7;
                    int j4 = (q & 127) << 2;
                    *(float4*)&w_s[kk][j4] =
                        *(const float4*)(d_whhT + (size_t)(kt * 16 + kk) * 512 + j4);
                }
                __syncthreads();
#pragma unroll
                for (int kk = 0; kk < 16; kk++) {
                    u64 hp[4];
#pragma unroll
                    for (int ri = 0; ri < 4; ri++)
                        hp[ri] = pack2(h_s[tr * 4 + ri][kt * 16 + kk]);
#pragma unroll
                    for (int gate = 0; gate < 4; gate++) {
                        float4 w = *(const float4*)&w_s[kk][gate * 128 + tc * 4];
                        u64 w01 = *(const u64*)&w.x;
                        u64 w23 = *(const u64*)&w.z;
#pragma unroll
                        for (int ri = 0; ri < 4; ri++) {
                            acc[gate][ri][0] = fma2(hp[ri], w01, acc[gate][ri][0]);
                            acc[gate][ri][1] = fma2(hp[ri], w23, acc[gate][ri][1]);
                        }
                    }
                }
            }
            __syncthreads();
        }

#pragma unroll
        for (int ri = 0; ri < 4; ri++) {
            float ig[4], fg[4], gg[4], og[4];
            float2 i01 = *(float2*)&acc[0][ri][0], i23 = *(float2*)&acc[0][ri][1];
            float2 f01 = *(float2*)&acc[1][ri][0], f23 = *(float2*)&acc[1][ri][1];
            float2 g01 = *(float2*)&acc[2][ri][0], g23 = *(float2*)&acc[2][ri][1];
            float2 o01 = *(float2*)&acc[3][ri][0], o23 = *(float2*)&acc[3][ri][1];
            ig[0]=i01.x; ig[1]=i01.y; ig[2]=i23.x; ig[3]=i23.y;
            fg[0]=f01.x; fg[1]=f01.y; fg[2]=f23.x; fg[3]=f23.y;
            gg[0]=g01.x; gg[1]=g01.y; gg[2]=g23.x; gg[3]=g23.y;
            og[0]=o01.x; og[1]=o01.y; og[2]=o23.x; og[3]=o23.y;
            float hn[4];
#pragma unroll
            for (int ci = 0; ci < 4; ci++) {
                float iv = sigmoidf_(ig[ci]);
                float fv = sigmoidf_(fg[ci]);
                float gv = tanhf(gg[ci]);
                float ov = sigmoidf_(og[ci]);
                float cn = fv * c[ri][ci] + iv * gv;
                c[ri][ci] = cn;
                hn[ci] = ov * tanhf(cn);
            }
            float4 hv4 = make_float4(hn[0], hn[1], hn[2], hn[3]);
            *(float4*)&h_s[tr * 4 + ri][tc * 4] = hv4;
            if (t == STEPS - 1)
                *(float4*)(d_hlast + (size_t)(row0 + ri) * 128 + tc * 4) = hv4;
        }
        __syncthreads();
    }
}

// ---------------- launch --------------------------------------------------------
extern "C" void kernel_launch(void* const* d_in, const int* in_sizes, int n_in,
                              void* d_out, int out_size)
{
    const float* x_seq = (const float*)d_in[0];
    const int*   ei    = (const int*)  d_in[1];
    const float* ew    = (const float*)d_in[2];
    const float* W0s   = (const float*)d_in[3];
    const float* b0s   = (const float*)d_in[4];
    const float* W0d   = (const float*)d_in[5];
    const float* b0d   = (const float*)d_in[6];
    const float* W1s   = (const float*)d_in[7];
    const float* b1s   = (const float*)d_in[8];
    const float* W1d   = (const float*)d_in[9];
    const float* b1d   = (const float*)d_in[10];
    const float* Wih   = (const float*)d_in[11];
    const float* Whh   = (const float*)d_in[12];
    const float* bih   = (const float*)d_in[13];
    const float* bhh   = (const float*)d_in[14];
    const float* Wp    = (const float*)d_in[15];
    const float* bp    = (const float*)d_in[16];
    float* out = (float*)d_out;

    float *aggf, *aggb, *h0, *h1, *gx, *hlast;
    cudaGetSymbolAddress((void**)&aggf,  d_aggf);
    cudaGetSymbolAddress((void**)&aggb,  d_aggb);
    cudaGetSymbolAddress((void**)&h0,    d_h0);
    cudaGetSymbolAddress((void**)&h1,    d_h1);
    cudaGetSymbolAddress((void**)&gx,    d_gx);
    cudaGetSymbolAddress((void**)&hlast, d_hlast);

    const int M = Gn * NN;   // 128000

    // ---- CSR build ----
    zero_kernel<<<(Gn * NN + 255) / 256, 256>>>();
    degcnt_kernel<<<(Gn * EE + 255) / 256, 256>>>(ei, ew);
    inv_kernel<<<(Gn * NN + 255) / 256, 256>>>();
    scan_kernel<<<dim3(Gn, 2), 1024>>>();
    scatter_kernel<<<(Gn * EE + 255) / 256, 256>>>(ei, ew);

    const int gblocks = (Gn * NN * 2 * 32 + 255) / 256;

    // ---- GCN layer 0 (F=64 -> H=128) ----
    gather_kernel<64><<<gblocks, 256>>>(x_seq);
    gemm2_kernel<64, true><<<dim3(M / 128, 1), 256>>>(
        aggf, aggb, W0s, W0d, b0s, b0d, h0, M, HD, 0.5f, 0.5f, 0.5f, 0.5f);

    // ---- GCN layer 1 (H=128 -> H=128) ----
    gather_kernel<128><<<gblocks, 256>>>(h0);
    gemm2_kernel<128, true><<<dim3(M / 128, 1), 256>>>(
        aggf, aggb, W1s, W1d, b1s, b1d, h1, M, HD, 0.5f, 0.5f, 0.5f, 0.5f);

    // ---- LSTM input GEMM: x@Wih.T + bih + bhh ----
    transpose_whh_kernel<<<(512 * 128 + 255) / 256, 256>>>(Whh);
    gemm2_kernel<128, false><<<dim3(M / 128, 4), 256>>>(
        h1, nullptr, Wih, nullptr, bih, bhh, gx, M, 4 * HD, 1.f, 0.f, 1.f, 1.f);

    // ---- LSTM recurrence ----
    lstm_kernel<<<BNR / 32, 256>>>();

    // ---- final projection [16000,128] @ Wp^T -> [B,N,64] ----
    gemm_small_kernel<128><<<BNR / 64, 256>>>(hlast, Wp, bp, out, BNR, FD0);
}